// round 15
// baseline (speedup 1.0000x reference)
#include <cuda_runtime.h>
#include <cstdint>

// dim=4096, MAX_DIM=32, N_COMP=10000.
// gather_idx/gather_sign: [32,32,32] row-major (k,i,j), int32/float32.
// Output: ricci[4096*4096] row-major + scalar trace at index 4096*4096.

#define DIMN 4096
#define MD   32
#define TPB  256

// Hybrid fill: TMA path + STG path concurrently.
//   blocks 0..7    : patch blocks, 4 rows each (rows 0..31) -> 1 x 64KB TMA
//   blocks 8..134  : fill blocks. Fill region = rows 32..4095 = 1016 x 64KB
//                    chunks. Each fill block: 5 TMA chunks (async, warps 0-4)
//                    + 3 STG chunks (all 256 threads) while TMA in flight.
//                    TMA chunks [0,635), STG chunks [635,1016).
#define PATCH_BLKS 8
#define FILL_BLKS  127
#define GRID       (PATCH_BLKS + FILL_BLKS)      // 135
#define SBUF_FLOATS 16384                         // 64KB
#define SBUF_BYTES  (SBUF_FLOATS * 4)
#define TMA_PER_BLK 5
#define STG_PER_BLK 3
#define TMA_CHUNKS  (FILL_BLKS * TMA_PER_BLK)     // 635
#define CHUNK_F4    (SBUF_FLOATS / 4)             // 4096 float4 per chunk

__device__ __forceinline__ void bulk_store(float* gdst, uint32_t ssrc, uint32_t bytes)
{
    asm volatile(
        "cp.async.bulk.global.shared::cta.bulk_group [%0], [%1], %2;"
        :: "l"(gdst), "r"(ssrc), "r"(bytes) : "memory");
}

__global__ __launch_bounds__(TPB)
void ricci_hybrid2_kernel(const float* __restrict__ comp,
                          const int*   __restrict__ gidx,
                          const float* __restrict__ gsgn,
                          float* __restrict__ out)
{
    extern __shared__ __align__(128) float sbuf[];       // 64KB dynamic

    const int b = blockIdx.x;
    const int t = threadIdx.x;

    // Zero the SMEM buffer.
    float4* s4 = reinterpret_cast<float4*>(sbuf);
    #pragma unroll
    for (int n = t; n < SBUF_FLOATS / 4; n += TPB)
        s4[n] = make_float4(0.f, 0.f, 0.f, 0.f);

    const uint32_t sbase = (uint32_t)__cvta_generic_to_shared(sbuf);
    float* const fill_base = out + (size_t)MD * DIMN;

    if (b >= PATCH_BLKS) {
        const int fb = b - PATCH_BLKS;            // 0..126
        __syncthreads();

        // Launch 5 async TMA chunks (warps 0..4, lane 0 each).
        const bool issuer = ((t & 31) == 0) && (t < TMA_PER_BLK * 32);
        if (issuer) {
            const int w = t >> 5;                 // 0..4
            asm volatile("fence.proxy.async.shared::cta;" ::: "memory");
            float* gdst = fill_base
                        + ((size_t)fb * TMA_PER_BLK + w) * SBUF_FLOATS;
            bulk_store(gdst, sbase, SBUF_BYTES);
            asm volatile("cp.async.bulk.commit_group;" ::: "memory");
        }

        // Concurrently: STG-write 3 chunks of zeros (different path/region).
        {
            float4* gdst4 = reinterpret_cast<float4*>(
                fill_base + ((size_t)TMA_CHUNKS + (size_t)fb * STG_PER_BLK)
                          * SBUF_FLOATS);
            const float4 z = make_float4(0.f, 0.f, 0.f, 0.f);
            #pragma unroll 4
            for (int n = t; n < STG_PER_BLK * CHUNK_F4; n += TPB)
                gdst4[n] = z;
        }

        // SMEM-source-read safety before exit.
        if (issuer)
            asm volatile("cp.async.bulk.wait_group.read 0;" ::: "memory");
        __syncthreads();
        return;
    }

    // Patch block: rows 4b..4b+3. Threads 0..127 compute one element each.
    if (t < 128) {
        const int i = 4 * b + (t >> 5);
        const int j = t & 31;
        float r = 0.f;
        #pragma unroll
        for (int k = 0; k < MD; k++) {
            const int o = k * (MD * MD) + i * MD + j;
            r += gsgn[o] * comp[gidx[o]];
        }
        sbuf[(t >> 5) * DIMN + j] = r;
    }

    // Block 0, warp 5 (threads 160..191): trace scalar via shuffle reduce
    // (fixed order -> deterministic). Scalar lies outside the bulk region.
    if (b == 0 && t >= 160 && t < 192) {
        const int d = t - 160;
        float s = 0.f;
        #pragma unroll
        for (int k = 0; k < MD; k++) {
            const int o = k * (MD * MD) + d * MD + d;
            s += gsgn[o] * comp[gidx[o]];
        }
        #pragma unroll
        for (int off = 16; off > 0; off >>= 1)
            s += __shfl_down_sync(0xFFFFFFFFu, s, off);
        if (d == 0) out[(size_t)DIMN * DIMN] = s;
    }

    __syncthreads();
    if (t == 0) {
        asm volatile("fence.proxy.async.shared::cta;" ::: "memory");
        bulk_store(out + (size_t)b * SBUF_FLOATS, sbase, SBUF_BYTES);
        asm volatile("cp.async.bulk.commit_group;" ::: "memory");
        asm volatile("cp.async.bulk.wait_group.read 0;" ::: "memory");
    }
    __syncthreads();
}

extern "C" void kernel_launch(void* const* d_in, const int* in_sizes, int n_in,
                              void* d_out, int out_size)
{
    const float* comp = (const float*)d_in[0];   // components [10000] f32
    const int*   gidx = (const int*)  d_in[1];   // gather_idx [32,32,32] i32
    const float* gsgn = (const float*)d_in[2];   // gather_sign [32,32,32] f32

    float* out = (float*)d_out;

    cudaFuncSetAttribute(ricci_hybrid2_kernel,
                         cudaFuncAttributeMaxDynamicSharedMemorySize,
                         SBUF_BYTES);

    ricci_hybrid2_kernel<<<GRID, TPB, SBUF_BYTES>>>(comp, gidx, gsgn, out);
}

// round 17
// speedup vs baseline: 1.0612x; 1.0612x over previous
#include <cuda_runtime.h>
#include <cstdint>

// dim=4096, MAX_DIM=32, N_COMP=10000.
// gather_idx/gather_sign: [32,32,32] row-major (k,i,j), int32/float32.
// Output: ricci[4096*4096] row-major + scalar trace at index 4096*4096.

#define DIMN 4096
#define MD   32
#define TPB  256

// Block-specialized hybrid fill (separate SMs per store path):
//   blocks 0..7     : patch blocks, 4 rows each (rows 0..31) -> 1 x 64KB TMA
//   blocks 8..86    : TMA fill blocks, 8 x 64KB each (chunks [0,632))
//   blocks 87..134  : STG fill blocks, 8 x 64KB each (chunks [632,1016))
// Fill region rows 32..4095 = 1016 x 64KB chunks; 632+384 = 1016 exactly.
#define PATCH_BLKS 8
#define TMA_BLKS   79
#define STG_BLKS   48
#define GRID       (PATCH_BLKS + TMA_BLKS + STG_BLKS)   // 135
#define SBUF_FLOATS 16384                                // 64KB
#define SBUF_BYTES  (SBUF_FLOATS * 4)
#define CHUNKS_PER_BLK 8
#define TMA_CHUNKS  (TMA_BLKS * CHUNKS_PER_BLK)          // 632
#define CHUNK_F4    (SBUF_FLOATS / 4)                    // 4096 float4/chunk

__device__ __forceinline__ void bulk_store(float* gdst, uint32_t ssrc, uint32_t bytes)
{
    asm volatile(
        "cp.async.bulk.global.shared::cta.bulk_group [%0], [%1], %2;"
        :: "l"(gdst), "r"(ssrc), "r"(bytes) : "memory");
}

__global__ __launch_bounds__(TPB)
void ricci_split2_kernel(const float* __restrict__ comp,
                         const int*   __restrict__ gidx,
                         const float* __restrict__ gsgn,
                         float* __restrict__ out)
{
    extern __shared__ __align__(128) float sbuf[];       // 64KB dynamic

    const int b = blockIdx.x;
    const int t = threadIdx.x;
    float* const fill_base = out + (size_t)MD * DIMN;

    if (b >= PATCH_BLKS + TMA_BLKS) {
        // STG fill block: 8 x 64KB of zeros via float4 stores, no SMEM use.
        const int fb = b - (PATCH_BLKS + TMA_BLKS);      // 0..47
        float4* gdst4 = reinterpret_cast<float4*>(
            fill_base + ((size_t)TMA_CHUNKS + (size_t)fb * CHUNKS_PER_BLK)
                      * SBUF_FLOATS);
        const float4 z = make_float4(0.f, 0.f, 0.f, 0.f);
        #pragma unroll 8
        for (int n = t; n < CHUNKS_PER_BLK * CHUNK_F4; n += TPB)
            gdst4[n] = z;
        return;
    }

    // TMA-path blocks need the zeroed SMEM buffer.
    float4* s4 = reinterpret_cast<float4*>(sbuf);
    #pragma unroll
    for (int n = t; n < SBUF_FLOATS / 4; n += TPB)
        s4[n] = make_float4(0.f, 0.f, 0.f, 0.f);

    const uint32_t sbase = (uint32_t)__cvta_generic_to_shared(sbuf);

    if (b >= PATCH_BLKS) {
        // TMA fill block: 8 x 64KB bulk stores, one per warp.
        const int fb = b - PATCH_BLKS;                   // 0..78
        __syncthreads();
        if ((t & 31) == 0) {
            const int w = t >> 5;                        // 0..7
            asm volatile("fence.proxy.async.shared::cta;" ::: "memory");
            float* gdst = fill_base
                        + ((size_t)fb * CHUNKS_PER_BLK + w) * SBUF_FLOATS;
            bulk_store(gdst, sbase, SBUF_BYTES);
            asm volatile("cp.async.bulk.commit_group;" ::: "memory");
            asm volatile("cp.async.bulk.wait_group.read 0;" ::: "memory");
        }
        __syncthreads();
        return;
    }

    // Patch block: rows 4b..4b+3. Threads 0..127 compute one element each.
    if (t < 128) {
        const int i = 4 * b + (t >> 5);
        const int j = t & 31;
        float r = 0.f;
        #pragma unroll
        for (int k = 0; k < MD; k++) {
            const int o = k * (MD * MD) + i * MD + j;
            r += gsgn[o] * comp[gidx[o]];
        }
        sbuf[(t >> 5) * DIMN + j] = r;
    }

    // Block 0, warp 5 (threads 160..191): trace scalar via shuffle reduce
    // (fixed order -> deterministic). Scalar lies outside the bulk region.
    if (b == 0 && t >= 160 && t < 192) {
        const int d = t - 160;
        float s = 0.f;
        #pragma unroll
        for (int k = 0; k < MD; k++) {
            const int o = k * (MD * MD) + d * MD + d;
            s += gsgn[o] * comp[gidx[o]];
        }
        #pragma unroll
        for (int off = 16; off > 0; off >>= 1)
            s += __shfl_down_sync(0xFFFFFFFFu, s, off);
        if (d == 0) out[(size_t)DIMN * DIMN] = s;
    }

    __syncthreads();
    if (t == 0) {
        asm volatile("fence.proxy.async.shared::cta;" ::: "memory");
        bulk_store(out + (size_t)b * SBUF_FLOATS, sbase, SBUF_BYTES);
        asm volatile("cp.async.bulk.commit_group;" ::: "memory");
        asm volatile("cp.async.bulk.wait_group.read 0;" ::: "memory");
    }
    __syncthreads();
}

extern "C" void kernel_launch(void* const* d_in, const int* in_sizes, int n_in,
                              void* d_out, int out_size)
{
    const float* comp = (const float*)d_in[0];   // components [10000] f32
    const int*   gidx = (const int*)  d_in[1];   // gather_idx [32,32,32] i32
    const float* gsgn = (const float*)d_in[2];   // gather_sign [32,32,32] f32

    float* out = (float*)d_out;

    cudaFuncSetAttribute(ricci_split2_kernel,
                         cudaFuncAttributeMaxDynamicSharedMemorySize,
                         SBUF_BYTES);

    ricci_split2_kernel<<<GRID, TPB, SBUF_BYTES>>>(comp, gidx, gsgn, out);
}